// round 2
// baseline (speedup 1.0000x reference)
#include <cuda_runtime.h>
#include <math.h>

#define NTOK   343
#define NHEADS 6
#define HD     32
#define CDIM   192
#define MROWS  43904   // 128 windows * 343 tokens
#define LTOK   21952

// ---------------- scratch (static device arrays; no allocation) ----------------
__device__ float d_q[8429568];
__device__ float d_k[8429568];
__device__ float d_v[8429568];
__device__ float d_hb[2197 * 6];
__device__ float d_rpb[6 * NTOK * NTOK];
__device__ float d_attn[MROWS * CDIM];
__device__ float d_tmp[MROWS * CDIM];
__device__ float d_x1[MROWS * CDIM];
__device__ float d_hid[MROWS * 768];

// -------- helpers --------
__device__ __forceinline__ int regcls(int c) { return c < 21 ? 0 : (c < 25 ? 1 : 2); }

__device__ __forceinline__ float cpb_coord(int i) {
    float x = (float)(i - 6) * (8.0f / 6.0f);
    return copysignf(log2f(fabsf(x) + 1.0f) * (1.0f / 3.0f), x);
}

// map window-token row m -> source/destination token row in [B, L]
// (roll by -3 then window partition on input; same map applies to output since
//  window_reverse followed by roll +3 is the exact inverse arrangement)
__device__ __forceinline__ int gather_row(int m) {
    int b_ = m / 343;  int n = m - b_ * 343;
    int b  = b_ >> 6;  int widx = b_ & 63;
    int th = n / 49;   int rem = n - th * 49;
    int tw = rem / 7;  int td = rem - tw * 7;
    int hh = ((widx >> 4) * 7 + th + 3) % 28;
    int wc = (((widx >> 2) & 3) * 7 + tw + 3) % 28;
    int dc = ((widx & 3) * 7 + td + 3) % 28;
    return b * LTOK + (hh * 28 + wc) * 28 + dc;
}

// ---------------- CPB MLP: hb[2197][6] ----------------
__global__ void __launch_bounds__(256) cpb_kernel(const float* __restrict__ w1,
                                                  const float* __restrict__ b1,
                                                  const float* __restrict__ w2) {
    int row = blockIdx.x * 8 + (threadIdx.x >> 5);
    if (row >= 2197) return;
    int lane = threadIdx.x & 31;
    int dh = row / 169; int rem = row - dh * 169;
    int dw = rem / 13;  int dd = rem - dw * 13;
    float c0 = cpb_coord(dh), c1 = cpb_coord(dw), c2 = cpb_coord(dd);
    float a0 = 0, a1 = 0, a2 = 0, a3 = 0, a4 = 0, a5 = 0;
    for (int i = lane; i < 512; i += 32) {
        float hv = c0 * w1[i * 3] + c1 * w1[i * 3 + 1] + c2 * w1[i * 3 + 2] + b1[i];
        hv = fmaxf(hv, 0.0f);
        a0 = fmaf(hv, w2[i], a0);
        a1 = fmaf(hv, w2[512 + i], a1);
        a2 = fmaf(hv, w2[1024 + i], a2);
        a3 = fmaf(hv, w2[1536 + i], a3);
        a4 = fmaf(hv, w2[2048 + i], a4);
        a5 = fmaf(hv, w2[2560 + i], a5);
    }
    #pragma unroll
    for (int o = 16; o; o >>= 1) {
        a0 += __shfl_xor_sync(0xffffffffu, a0, o);
        a1 += __shfl_xor_sync(0xffffffffu, a1, o);
        a2 += __shfl_xor_sync(0xffffffffu, a2, o);
        a3 += __shfl_xor_sync(0xffffffffu, a3, o);
        a4 += __shfl_xor_sync(0xffffffffu, a4, o);
        a5 += __shfl_xor_sync(0xffffffffu, a5, o);
    }
    if (lane == 0) {
        d_hb[row * 6 + 0] = a0; d_hb[row * 6 + 1] = a1; d_hb[row * 6 + 2] = a2;
        d_hb[row * 6 + 3] = a3; d_hb[row * 6 + 4] = a4; d_hb[row * 6 + 5] = a5;
    }
}

// ---------------- expand rpb[h][i][j] = 16*sigmoid(hb[rpi(i,j)][h]) ----------------
__global__ void __launch_bounds__(256) rpb_kernel() {
    int g = blockIdx.x * 256 + threadIdx.x;
    if (g >= 6 * NTOK * NTOK) return;
    int h = g / (NTOK * NTOK); int rem = g - h * NTOK * NTOK;
    int i = rem / NTOK; int j = rem - i * NTOK;
    int ih = i / 49, iw = (i / 7) % 7, id = i % 7;
    int jh = j / 49, jw = (j / 7) % 7, jd = j % 7;
    int idx = (ih - jh + 6) * 169 + (iw - jw + 6) * 13 + (id - jd + 6);
    float x = d_hb[idx * 6 + h];
    d_rpb[g] = 16.0f / (1.0f + expf(-x));
}

// ---------------- tiled GEMM: C[m,n] = A[m,:] . W[n,:] (+ epilogues) ----------------
// EPI: 0 = +bias store, 1 = +bias GELU store, 2 = qkv scatter (q/k/v + q/v bias)
template <bool GATHER, int EPI>
__global__ void __launch_bounds__(256) gemm_k(const float* __restrict__ A,
                                              const float* __restrict__ W,
                                              const float* __restrict__ bias,
                                              float* __restrict__ C,
                                              int K, int Nout,
                                              const float* __restrict__ qb,
                                              const float* __restrict__ vb) {
    __shared__ __align__(16) float As[16][68];
    __shared__ __align__(16) float Bs[16][68];
    int t = threadIdx.x;
    int n0 = blockIdx.x * 64, m0 = blockIdx.y * 64;
    int lr = t >> 2, lk = (t & 3) * 4;
    const float* aptr;
    if (GATHER) aptr = A + (size_t)gather_row(m0 + lr) * K + lk;
    else        aptr = A + (size_t)(m0 + lr) * K + lk;
    const float* bptr = W + (size_t)(n0 + lr) * K + lk;
    int tm = (t >> 4) * 4, tn = (t & 15) * 4;
    float acc[4][4];
    #pragma unroll
    for (int i = 0; i < 4; i++)
        #pragma unroll
        for (int j = 0; j < 4; j++) acc[i][j] = 0.0f;

    for (int k0 = 0; k0 < K; k0 += 16) {
        float4 a4 = *(const float4*)(aptr + k0);
        float4 b4 = *(const float4*)(bptr + k0);
        __syncthreads();
        As[lk + 0][lr] = a4.x; As[lk + 1][lr] = a4.y; As[lk + 2][lr] = a4.z; As[lk + 3][lr] = a4.w;
        Bs[lk + 0][lr] = b4.x; Bs[lk + 1][lr] = b4.y; Bs[lk + 2][lr] = b4.z; Bs[lk + 3][lr] = b4.w;
        __syncthreads();
        #pragma unroll
        for (int kk = 0; kk < 16; kk++) {
            float4 af = *(const float4*)&As[kk][tm];
            float4 bf = *(const float4*)&Bs[kk][tn];
            acc[0][0] = fmaf(af.x, bf.x, acc[0][0]); acc[0][1] = fmaf(af.x, bf.y, acc[0][1]);
            acc[0][2] = fmaf(af.x, bf.z, acc[0][2]); acc[0][3] = fmaf(af.x, bf.w, acc[0][3]);
            acc[1][0] = fmaf(af.y, bf.x, acc[1][0]); acc[1][1] = fmaf(af.y, bf.y, acc[1][1]);
            acc[1][2] = fmaf(af.y, bf.z, acc[1][2]); acc[1][3] = fmaf(af.y, bf.w, acc[1][3]);
            acc[2][0] = fmaf(af.z, bf.x, acc[2][0]); acc[2][1] = fmaf(af.z, bf.y, acc[2][1]);
            acc[2][2] = fmaf(af.z, bf.z, acc[2][2]); acc[2][3] = fmaf(af.z, bf.w, acc[2][3]);
            acc[3][0] = fmaf(af.w, bf.x, acc[3][0]); acc[3][1] = fmaf(af.w, bf.y, acc[3][1]);
            acc[3][2] = fmaf(af.w, bf.z, acc[3][2]); acc[3][3] = fmaf(af.w, bf.w, acc[3][3]);
        }
    }

    #pragma unroll
    for (int i = 0; i < 4; i++) {
        int mm = m0 + tm + i;
        #pragma unroll
        for (int j = 0; j < 4; j++) {
            int nn = n0 + tn + j;
            float v = acc[i][j];
            if (EPI == 0) {
                C[(size_t)mm * Nout + nn] = v + bias[nn];
            } else if (EPI == 1) {
                v += bias[nn];
                C[(size_t)mm * Nout + nn] = 0.5f * v * (1.0f + erff(v * 0.70710678f));
            } else {
                int sec = nn / 192; int cc = nn - sec * 192;
                float bv = (sec == 0) ? qb[cc] : (sec == 2 ? vb[cc] : 0.0f);
                v += bv;
                int b_ = mm / 343; int n = mm - b_ * 343;
                int head = cc >> 5; int dd = cc & 31;
                size_t dst = ((size_t)(b_ * 6 + head) * 343 + n) * 32 + dd;
                if (sec == 0) d_q[dst] = v;
                else if (sec == 1) d_k[dst] = v;
                else d_v[dst] = v;
            }
        }
    }
}

// ---------------- attention: one block per (window, head) ----------------
__global__ void __launch_bounds__(256) attn_kernel(const float* __restrict__ logit_scale) {
    extern __shared__ float sm[];
    float* kT  = sm;             // [32][343] normalized k, transposed
    float* vs  = sm + 10976;     // [343][32]
    float* scb = sm + 21952;     // 8 warps * [343][4] scores
    float* qTb = sm + 32928;     // 8 warps * [32][4] q rows (transposed)
    int*   rv  = (int*)(sm + 33952);  // [343] region label

    int bh = blockIdx.x;
    int b_ = bh / 6, h = bh - b_ * 6;
    int t = threadIdx.x, w = t >> 5, lane = t & 31;
    size_t base = (size_t)(b_ * 6 + h) * NTOK * HD;

    for (int i = t; i < NTOK * HD; i += 256) vs[i] = d_v[base + i];

    for (int j = w; j < NTOK; j += 8) {
        float kv = d_k[base + j * 32 + lane];
        float ss = kv * kv;
        #pragma unroll
        for (int o = 16; o; o >>= 1) ss += __shfl_xor_sync(0xffffffffu, ss, o);
        kT[lane * NTOK + j] = kv * (1.0f / fmaxf(sqrtf(ss), 1e-12f));
    }

    int widx = b_ & 63;
    int wh = widx >> 4, ww = (widx >> 2) & 3, wd = widx & 3;
    for (int n = t; n < NTOK; n += 256) {
        int th = n / 49; int rem = n - th * 49;
        int tw = rem / 7; int td = rem - tw * 7;
        rv[n] = regcls(wh * 7 + th) * 9 + regcls(ww * 7 + tw) * 3 + regcls(wd * 7 + td);
    }
    __syncthreads();

    float scale = expf(fminf(logit_scale[h], 4.6051702f));
    float* sc = scb + w * 1372;
    float* qT = qTb + w * 128;
    const float* rpbh = d_rpb + (size_t)h * NTOK * NTOK;
    int b = b_ >> 6;

    for (int g = w; g * 4 < NTOK; g += 8) {
        int row0 = g * 4;
        int nr = NTOK - row0; if (nr > 4) nr = 4;
        int rowv[4], outl[4], rvr[4];
        #pragma unroll
        for (int r = 0; r < 4; r++) {
            int row = row0 + (r < nr ? r : 0);
            rowv[r] = row;
            float qv = d_q[base + row * 32 + lane];
            float ss = qv * qv;
            #pragma unroll
            for (int o = 16; o; o >>= 1) ss += __shfl_xor_sync(0xffffffffu, ss, o);
            qv = qv * (1.0f / fmaxf(sqrtf(ss), 1e-12f)) * scale;
            qT[lane * 4 + r] = qv;
            int th = row / 49; int rem = row - th * 49;
            int tw = rem / 7;  int td = rem - tw * 7;
            int hh = (wh * 7 + th + 3) % 28;
            int wc = (ww * 7 + tw + 3) % 28;
            int dc = (wd * 7 + td + 3) % 28;
            outl[r] = b * LTOK + (hh * 28 + wc) * 28 + dc;
            rvr[r] = rv[row];
        }
        __syncwarp();

        // scores S[r][j] = qn[r] . knT[:,j] * scale  + rpb + mask
        for (int jt = 0; jt < 11; jt++) {
            int j = jt * 32 + lane;
            int jc = j < NTOK ? j : NTOK - 1;
            float a0 = 0, a1 = 0, a2 = 0, a3 = 0;
            #pragma unroll
            for (int d = 0; d < 32; d++) {
                float kv = kT[d * NTOK + jc];
                float4 q4 = *(const float4*)&qT[d * 4];
                a0 = fmaf(q4.x, kv, a0); a1 = fmaf(q4.y, kv, a1);
                a2 = fmaf(q4.z, kv, a2); a3 = fmaf(q4.w, kv, a3);
            }
            if (j < NTOK) {
                int rj = rv[j];
                a0 += rpbh[(size_t)rowv[0] * NTOK + j] + (rvr[0] != rj ? -100.0f : 0.0f);
                a1 += rpbh[(size_t)rowv[1] * NTOK + j] + (rvr[1] != rj ? -100.0f : 0.0f);
                a2 += rpbh[(size_t)rowv[2] * NTOK + j] + (rvr[2] != rj ? -100.0f : 0.0f);
                a3 += rpbh[(size_t)rowv[3] * NTOK + j] + (rvr[3] != rj ? -100.0f : 0.0f);
                *(float4*)&sc[j * 4] = make_float4(a0, a1, a2, a3);
            }
        }
        __syncwarp();

        // softmax per row
        float rsum[4];
        #pragma unroll
        for (int r = 0; r < 4; r++) {
            float mx = -1e30f;
            for (int jt = 0; jt < 11; jt++) {
                int j = jt * 32 + lane;
                if (j < NTOK) mx = fmaxf(mx, sc[j * 4 + r]);
            }
            #pragma unroll
            for (int o = 16; o; o >>= 1) mx = fmaxf(mx, __shfl_xor_sync(0xffffffffu, mx, o));
            float s = 0;
            for (int jt = 0; jt < 11; jt++) {
                int j = jt * 32 + lane;
                if (j < NTOK) {
                    float e = expf(sc[j * 4 + r] - mx);
                    sc[j * 4 + r] = e;
                    s += e;
                }
            }
            #pragma unroll
            for (int o = 16; o; o >>= 1) s += __shfl_xor_sync(0xffffffffu, s, o);
            rsum[r] = 1.0f / s;
        }
        __syncwarp();

        // PV
        float o0 = 0, o1 = 0, o2 = 0, o3 = 0;
        #pragma unroll 7
        for (int j = 0; j < NTOK; j++) {
            float4 p4 = *(const float4*)&sc[j * 4];
            float vvv = vs[j * 32 + lane];
            o0 = fmaf(p4.x, vvv, o0); o1 = fmaf(p4.y, vvv, o1);
            o2 = fmaf(p4.z, vvv, o2); o3 = fmaf(p4.w, vvv, o3);
        }
        float oo[4] = {o0, o1, o2, o3};
        for (int r = 0; r < nr; r++)
            d_attn[(size_t)outl[r] * CDIM + h * 32 + lane] = oo[r] * rsum[r];
    }
}

// ---------------- LayerNorm(inp)*g+b + res ----------------
__global__ void __launch_bounds__(256) ln_res_kernel(const float* __restrict__ inp,
                                                     const float* __restrict__ res,
                                                     const float* __restrict__ g,
                                                     const float* __restrict__ bb,
                                                     float* __restrict__ out) {
    int row = blockIdx.x * 8 + (threadIdx.x >> 5);
    int lane = threadIdx.x & 31;
    const float* p = inp + (size_t)row * CDIM;
    float v[6]; float s = 0, s2 = 0;
    #pragma unroll
    for (int i = 0; i < 6; i++) {
        float x = p[lane + 32 * i];
        v[i] = x; s += x; s2 = fmaf(x, x, s2);
    }
    #pragma unroll
    for (int o = 16; o; o >>= 1) {
        s  += __shfl_xor_sync(0xffffffffu, s, o);
        s2 += __shfl_xor_sync(0xffffffffu, s2, o);
    }
    float mean = s * (1.0f / 192.0f);
    float var = s2 * (1.0f / 192.0f) - mean * mean;
    float rstd = rsqrtf(var + 1e-5f);
    const float* rr = res + (size_t)row * CDIM;
    float* oo = out + (size_t)row * CDIM;
    #pragma unroll
    for (int i = 0; i < 6; i++) {
        int c = lane + 32 * i;
        oo[c] = rr[c] + (v[i] - mean) * rstd * g[c] + bb[c];
    }
}

// ---------------- launch ----------------
extern "C" void kernel_launch(void* const* d_in, const int* in_sizes, int n_in,
                              void* d_out, int out_size) {
    const float* x       = (const float*)d_in[0];
    const float* qkv_w   = (const float*)d_in[1];
    const float* q_bias  = (const float*)d_in[2];
    const float* v_bias  = (const float*)d_in[3];
    const float* lscale  = (const float*)d_in[4];
    const float* cpb_w1  = (const float*)d_in[5];
    const float* cpb_b1  = (const float*)d_in[6];
    const float* cpb_w2  = (const float*)d_in[7];
    const float* proj_w  = (const float*)d_in[8];
    const float* proj_b  = (const float*)d_in[9];
    const float* n1g     = (const float*)d_in[10];
    const float* n1b     = (const float*)d_in[11];
    const float* fc1_w   = (const float*)d_in[12];
    const float* fc1_b   = (const float*)d_in[13];
    const float* fc2_w   = (const float*)d_in[14];
    const float* fc2_b   = (const float*)d_in[15];
    const float* n2g     = (const float*)d_in[16];
    const float* n2b     = (const float*)d_in[17];
    float* out = (float*)d_out;

    void *p_attn, *p_tmp, *p_x1, *p_hid;
    cudaGetSymbolAddress(&p_attn, d_attn);
    cudaGetSymbolAddress(&p_tmp, d_tmp);
    cudaGetSymbolAddress(&p_x1, d_x1);
    cudaGetSymbolAddress(&p_hid, d_hid);

    cpb_kernel<<<275, 256>>>(cpb_w1, cpb_b1, cpb_w2);
    rpb_kernel<<<2758, 256>>>();

    // QKV: gathered-A GEMM, scatter epilogue
    gemm_k<true, 2><<<dim3(9, 686), 256>>>(x, qkv_w, nullptr, nullptr, 192, 576, q_bias, v_bias);

    cudaFuncSetAttribute(attn_kernel, cudaFuncAttributeMaxDynamicSharedMemorySize, 137184);
    attn_kernel<<<768, 256, 137184>>>(lscale);

    // proj
    gemm_k<false, 0><<<dim3(3, 686), 256>>>((const float*)p_attn, proj_w, proj_b,
                                            (float*)p_tmp, 192, 192, nullptr, nullptr);
    // x1 = x + LN(proj)
    ln_res_kernel<<<5488, 256>>>((const float*)p_tmp, x, n1g, n1b, (float*)p_x1);
    // fc1 + GELU
    gemm_k<false, 1><<<dim3(12, 686), 256>>>((const float*)p_x1, fc1_w, fc1_b,
                                             (float*)p_hid, 192, 768, nullptr, nullptr);
    // fc2
    gemm_k<false, 0><<<dim3(3, 686), 256>>>((const float*)p_hid, fc2_w, fc2_b,
                                            (float*)p_tmp, 768, 192, nullptr, nullptr);
    // out = x1 + LN(fc2)
    ln_res_kernel<<<5488, 256>>>((const float*)p_tmp, (const float*)p_x1, n2g, n2b, out);
}

// round 4
// speedup vs baseline: 1.9926x; 1.9926x over previous
#include <cuda_runtime.h>
#include <cuda_bf16.h>
#include <math.h>
#include <stdint.h>

#define NTOK 343
#define CDIM 192
#define LTOK 21952
#define KSR  346   // kT row stride in bf16 elems (odd word stride -> conflict-free)

__device__ float d_q[8429568];
__device__ float d_k[8429568];
__device__ float d_v[8429568];
__device__ float d_hb[2197 * 6];
__device__ float d_rpb[6 * NTOK * NTOK];
__device__ float d_attn[43904 * 192];
__device__ float d_tmp[43904 * 192];
__device__ float d_x1[43904 * 192];
__device__ float d_hid[43904 * 768];

__device__ __forceinline__ int regcls(int c) { return c < 21 ? 0 : (c < 25 ? 1 : 2); }
__device__ __forceinline__ float cpb_coord(int i) {
    float x = (float)(i - 6) * (8.0f / 6.0f);
    return copysignf(log2f(fabsf(x) + 1.0f) * (1.0f / 3.0f), x);
}
__device__ __forceinline__ int gather_row(int m) {
    int b_ = m / 343;  int n = m - b_ * 343;
    int b  = b_ >> 6;  int widx = b_ & 63;
    int th = n / 49;   int rem = n - th * 49;
    int tw = rem / 7;  int td = rem - tw * 7;
    int hh = ((widx >> 4) * 7 + th + 3) % 28;
    int wc = (((widx >> 2) & 3) * 7 + tw + 3) % 28;
    int dc = ((widx & 3) * 7 + td + 3) % 28;
    return b * LTOK + (hh * 28 + wc) * 28 + dc;
}

__device__ __forceinline__ void mma16816(float* d, const uint32_t* a, const uint32_t* b) {
    asm volatile(
        "mma.sync.aligned.m16n8k16.row.col.f32.bf16.bf16.f32 "
        "{%0,%1,%2,%3}, {%4,%5,%6,%7}, {%8,%9}, {%0,%1,%2,%3};"
        : "+f"(d[0]), "+f"(d[1]), "+f"(d[2]), "+f"(d[3])
        : "r"(a[0]), "r"(a[1]), "r"(a[2]), "r"(a[3]), "r"(b[0]), "r"(b[1]));
}

// ---------------- CPB MLP ----------------
__global__ void __launch_bounds__(256) cpb_kernel(const float* __restrict__ w1,
                                                  const float* __restrict__ b1,
                                                  const float* __restrict__ w2) {
    int row = blockIdx.x * 8 + (threadIdx.x >> 5);
    if (row >= 2197) return;
    int lane = threadIdx.x & 31;
    int dh = row / 169; int rem = row - dh * 169;
    int dw = rem / 13;  int dd = rem - dw * 13;
    float c0 = cpb_coord(dh), c1 = cpb_coord(dw), c2 = cpb_coord(dd);
    float a0 = 0, a1 = 0, a2 = 0, a3 = 0, a4 = 0, a5 = 0;
    for (int i = lane; i < 512; i += 32) {
        float hv = c0 * w1[i * 3] + c1 * w1[i * 3 + 1] + c2 * w1[i * 3 + 2] + b1[i];
        hv = fmaxf(hv, 0.0f);
        a0 = fmaf(hv, w2[i], a0);        a1 = fmaf(hv, w2[512 + i], a1);
        a2 = fmaf(hv, w2[1024 + i], a2); a3 = fmaf(hv, w2[1536 + i], a3);
        a4 = fmaf(hv, w2[2048 + i], a4); a5 = fmaf(hv, w2[2560 + i], a5);
    }
    #pragma unroll
    for (int o = 16; o; o >>= 1) {
        a0 += __shfl_xor_sync(~0u, a0, o); a1 += __shfl_xor_sync(~0u, a1, o);
        a2 += __shfl_xor_sync(~0u, a2, o); a3 += __shfl_xor_sync(~0u, a3, o);
        a4 += __shfl_xor_sync(~0u, a4, o); a5 += __shfl_xor_sync(~0u, a5, o);
    }
    if (lane == 0) {
        d_hb[row * 6 + 0] = a0; d_hb[row * 6 + 1] = a1; d_hb[row * 6 + 2] = a2;
        d_hb[row * 6 + 3] = a3; d_hb[row * 6 + 4] = a4; d_hb[row * 6 + 5] = a5;
    }
}

__global__ void __launch_bounds__(256) rpb_kernel() {
    int g = blockIdx.x * 256 + threadIdx.x;
    if (g >= 6 * NTOK * NTOK) return;
    int h = g / (NTOK * NTOK); int rem = g - h * NTOK * NTOK;
    int i = rem / NTOK; int j = rem - i * NTOK;
    int ih = i / 49, iw = (i / 7) % 7, id = i % 7;
    int jh = j / 49, jw = (j / 7) % 7, jd = j % 7;
    int idx = (ih - jh + 6) * 169 + (iw - jw + 6) * 13 + (id - jd + 6);
    d_rpb[g] = 16.0f / (1.0f + __expf(-d_hb[idx * 6 + h]));
}

// ---------------- HMMA GEMM (bf16 split precision), tile 128x64 ----------------
// EPI: 0 = +bias, 1 = +bias GELU, 2 = qkv scatter
template <bool GATHER, int EPI>
__global__ void __launch_bounds__(256) gemm_mma(
    const float* __restrict__ A, const float* __restrict__ W,
    const float* __restrict__ bias, float* __restrict__ C,
    int Ktot, int Nout, int nchunks,
    const float* __restrict__ qb, const float* __restrict__ vb)
{
    __shared__ __nv_bfloat16 Ah[128][40], Al[128][40], Bh[64][40], Bl[64][40];
    int t = threadIdx.x, lane = t & 31, wid = t >> 5;
    int n0 = blockIdx.x * 64, m0 = blockIdx.y * 128;
    int wm = wid >> 1, wn = wid & 1;

    float acc[2][4][4];
    #pragma unroll
    for (int mf = 0; mf < 2; mf++)
        #pragma unroll
        for (int nf = 0; nf < 4; nf++)
            #pragma unroll
            for (int e = 0; e < 4; e++) acc[mf][nf][e] = 0.0f;

    // precompute A source rows (4 rows per thread)
    const float* arow[4];
    #pragma unroll
    for (int it = 0; it < 4; it++) {
        int row = (t + 256 * it) >> 3;
        int grow = GATHER ? gather_row(m0 + row) : (m0 + row);
        arow[it] = A + (size_t)grow * Ktot;
    }
    const float* brow[2];
    #pragma unroll
    for (int it = 0; it < 2; it++) {
        int row = (t + 256 * it) >> 3;
        brow[it] = W + (size_t)(n0 + row) * Ktot;
    }

    int rA = wm * 32 + (lane >> 2);          // a-frag row base (within tile)
    int kA = (lane & 3) * 2;                 // a-frag k base
    int cB = wn * 32 + (lane >> 2);          // b-frag col base

    for (int kc = 0; kc < nchunks; kc++) {
        #pragma unroll
        for (int it = 0; it < 4; it++) {
            int i = t + 256 * it;
            int row = i >> 3, c4 = i & 7;
            float4 v = *(const float4*)(arow[it] + kc * 32 + c4 * 4);
            __nv_bfloat16 h0 = __float2bfloat16_rn(v.x), h1 = __float2bfloat16_rn(v.y);
            __nv_bfloat16 h2 = __float2bfloat16_rn(v.z), h3 = __float2bfloat16_rn(v.w);
            *(__nv_bfloat162*)&Ah[row][c4 * 4]     = __halves2bfloat162(h0, h1);
            *(__nv_bfloat162*)&Ah[row][c4 * 4 + 2] = __halves2bfloat162(h2, h3);
            *(__nv_bfloat162*)&Al[row][c4 * 4]     = __floats2bfloat162_rn(v.x - __bfloat162float(h0), v.y - __bfloat162float(h1));
            *(__nv_bfloat162*)&Al[row][c4 * 4 + 2] = __floats2bfloat162_rn(v.z - __bfloat162float(h2), v.w - __bfloat162float(h3));
        }
        #pragma unroll
        for (int it = 0; it < 2; it++) {
            int i = t + 256 * it;
            int row = i >> 3, c4 = i & 7;
            float4 v = *(const float4*)(brow[it] + kc * 32 + c4 * 4);
            __nv_bfloat16 h0 = __float2bfloat16_rn(v.x), h1 = __float2bfloat16_rn(v.y);
            __nv_bfloat16 h2 = __float2bfloat16_rn(v.z), h3 = __float2bfloat16_rn(v.w);
            *(__nv_bfloat162*)&Bh[row][c4 * 4]     = __halves2bfloat162(h0, h1);
            *(__nv_bfloat162*)&Bh[row][c4 * 4 + 2] = __halves2bfloat162(h2, h3);
            *(__nv_bfloat162*)&Bl[row][c4 * 4]     = __floats2bfloat162_rn(v.x - __bfloat162float(h0), v.y - __bfloat162float(h1));
            *(__nv_bfloat162*)&Bl[row][c4 * 4 + 2] = __floats2bfloat162_rn(v.z - __bfloat162float(h2), v.w - __bfloat162float(h3));
        }
        __syncthreads();

        #pragma unroll
        for (int ks = 0; ks < 2; ks++) {
            int kb = ks * 16 + kA;
            uint32_t ah[2][4], al[2][4];
            #pragma unroll
            for (int mf = 0; mf < 2; mf++) {
                int r = rA + mf * 16;
                ah[mf][0] = *(const uint32_t*)&Ah[r][kb];
                ah[mf][1] = *(const uint32_t*)&Ah[r + 8][kb];
                ah[mf][2] = *(const uint32_t*)&Ah[r][kb + 8];
                ah[mf][3] = *(const uint32_t*)&Ah[r + 8][kb + 8];
                al[mf][0] = *(const uint32_t*)&Al[r][kb];
                al[mf][1] = *(const uint32_t*)&Al[r + 8][kb];
                al[mf][2] = *(const uint32_t*)&Al[r][kb + 8];
                al[mf][3] = *(const uint32_t*)&Al[r + 8][kb + 8];
            }
            #pragma unroll
            for (int nf = 0; nf < 4; nf++) {
                int c = cB + nf * 8;
                uint32_t bh[2], bl[2];
                bh[0] = *(const uint32_t*)&Bh[c][kb];
                bh[1] = *(const uint32_t*)&Bh[c][kb + 8];
                bl[0] = *(const uint32_t*)&Bl[c][kb];
                bl[1] = *(const uint32_t*)&Bl[c][kb + 8];
                #pragma unroll
                for (int mf = 0; mf < 2; mf++) {
                    mma16816(acc[mf][nf], ah[mf], bh);
                    mma16816(acc[mf][nf], al[mf], bh);
                    mma16816(acc[mf][nf], ah[mf], bl);
                }
            }
        }
        __syncthreads();
    }

    // epilogue
    int rbase = m0 + wm * 32 + (lane >> 2);
    int cbase = n0 + wn * 32 + (lane & 3) * 2;
    int sec = 0;
    if (EPI == 2) sec = n0 / 192;
    #pragma unroll
    for (int mf = 0; mf < 2; mf++) {
        #pragma unroll
        for (int half = 0; half < 2; half++) {
            int row = rbase + mf * 16 + half * 8;
            #pragma unroll
            for (int nf = 0; nf < 4; nf++) {
                int col = cbase + nf * 8;
                float v0 = acc[mf][nf][half * 2 + 0];
                float v1 = acc[mf][nf][half * 2 + 1];
                if (EPI == 2) {
                    int cc = col - sec * 192;
                    int head = cc >> 5, dd = cc & 31;
                    int b_ = row / 343; int n = row - b_ * 343;
                    size_t dst = ((size_t)(b_ * 6 + head) * 343 + n) * 32 + dd;
                    float* dp = (sec == 0) ? d_q : (sec == 1 ? d_k : d_v);
                    if (sec == 0) { v0 += qb[cc]; v1 += qb[cc + 1]; }
                    else if (sec == 2) { v0 += vb[cc]; v1 += vb[cc + 1]; }
                    *(float2*)(dp + dst) = make_float2(v0, v1);
                } else {
                    v0 += bias[col]; v1 += bias[col + 1];
                    if (EPI == 1) {
                        v0 = 0.5f * v0 * (1.0f + erff(v0 * 0.70710678f));
                        v1 = 0.5f * v1 * (1.0f + erff(v1 * 0.70710678f));
                    }
                    *(float2*)&C[(size_t)row * Nout + col] = make_float2(v0, v1);
                }
            }
        }
    }
}

// ---------------- attention: 224 threads, 2 CTAs/SM ----------------
__global__ void __launch_bounds__(224, 2) attn_kernel(const float* __restrict__ logit_scale) {
    extern __shared__ char smraw[];
    __nv_bfloat16* kT = (__nv_bfloat16*)smraw;           // [32][346] bf16
    float* vs  = (float*)(smraw + 22144);                // [343][32]
    float* scb = (float*)(smraw + 66048);                // 7 x [343][4]
    float* qTb = (float*)(smraw + 104464);               // 7 x [32][4]
    int*   rv  = (int*)(smraw + 108048);                 // [344]

    int bh = blockIdx.x;
    int b_ = bh / 6, h = bh - b_ * 6;
    int t = threadIdx.x, w = t >> 5, lane = t & 31;
    size_t base = (size_t)(b_ * 6 + h) * NTOK * 32;

    for (int i = t; i < NTOK * 32; i += 224) vs[i] = d_v[base + i];
    for (int j = w; j < NTOK; j += 7) {
        float kv = d_k[base + j * 32 + lane];
        float ss = kv * kv;
        #pragma unroll
        for (int o = 16; o; o >>= 1) ss += __shfl_xor_sync(~0u, ss, o);
        kT[lane * KSR + j] = __float2bfloat16(kv * (1.0f / fmaxf(sqrtf(ss), 1e-12f)));
    }
    if (t < 32) kT[t * KSR + 343] = __float2bfloat16(0.f);
    int widx = b_ & 63;
    int wh = widx >> 4, ww = (widx >> 2) & 3, wd = widx & 3;
    for (int n = t; n < NTOK; n += 224) {
        int th = n / 49; int rem = n - th * 49;
        int tw = rem / 7; int td = rem - tw * 7;
        rv[n] = regcls(wh * 7 + th) * 9 + regcls(ww * 7 + tw) * 3 + regcls(wd * 7 + td);
    }
    __syncthreads();

    float scale = __expf(fminf(logit_scale[h], 4.6051702f));
    float* sc = scb + w * 1372;
    float* qT = qTb + w * 128;
    const float* rpbh = d_rpb + (size_t)h * NTOK * NTOK;
    int b = b_ >> 6;
    int pc[6];
    #pragma unroll
    for (int u = 0; u < 6; u++) { int p = lane + 32 * u; pc[u] = p > 171 ? 171 : p; }

    for (int g = w; g * 4 < NTOK; g += 7) {
        int row0 = g * 4;
        int nr = NTOK - row0; if (nr > 4) nr = 4;
        int rowv[4], outl[4], rvr[4];
        #pragma unroll
        for (int r = 0; r < 4; r++) {
            int row = row0 + (r < nr ? r : 0);
            rowv[r] = row;
            float qv = d_q[base + row * 32 + lane];
            float ss = qv * qv;
            #pragma unroll
            for (int o = 16; o; o >>= 1) ss += __shfl_xor_sync(~0u, ss, o);
            qT[lane * 4 + r] = qv * (1.0f / fmaxf(sqrtf(ss), 1e-12f)) * scale;
            int th = row / 49; int rem = row - th * 49;
            int tw = rem / 7;  int td = rem - tw * 7;
            outl[r] = b * LTOK + (((wh*7+th+3)%28) * 28 + ((ww*7+tw+3)%28)) * 28 + ((wd*7+td+3)%28);
            rvr[r] = rv[row];
        }
        __syncwarp();

        float2 acc[6][4];
        #pragma unroll
        for (int u = 0; u < 6; u++)
            #pragma unroll
            for (int r = 0; r < 4; r++) acc[u][r] = make_float2(0.f, 0.f);
        const __nv_bfloat162* kp = (const __nv_bfloat162*)kT;
        #pragma unroll 4
        for (int d = 0; d < 32; d++) {
            float4 q4 = *(const float4*)(qT + d * 4);
            int rb = d * (KSR / 2);
            #pragma unroll
            for (int u = 0; u < 6; u++) {
                float2 kf = __bfloat1622float2(kp[rb + pc[u]]);
                acc[u][0].x = fmaf(q4.x, kf.x, acc[u][0].x); acc[u][0].y = fmaf(q4.x, kf.y, acc[u][0].y);
                acc[u][1].x = fmaf(q4.y, kf.x, acc[u][1].x); acc[u][1].y = fmaf(q4.y, kf.y, acc[u][1].y);
                acc[u][2].x = fmaf(q4.z, kf.x, acc[u][2].x); acc[u][2].y = fmaf(q4.z, kf.y, acc[u][2].y);
                acc[u][3].x = fmaf(q4.w, kf.x, acc[u][3].x); acc[u][3].y = fmaf(q4.w, kf.y, acc[u][3].y);
            }
        }
        #pragma unroll
        for (int u = 0; u < 6; u++) {
            int p = lane + 32 * u;
            if (p > 171) break;
            int j0 = 2 * p, j1 = j0 + 1;
            int rj0 = rv[j0];
            float4 s0;
            s0.x = acc[u][0].x + rpbh[(size_t)rowv[0] * NTOK + j0] + (rvr[0] != rj0 ? -100.f : 0.f);
            s0.y = acc[u][1].x + rpbh[(size_t)rowv[1] * NTOK + j0] + (rvr[1] != rj0 ? -100.f : 0.f);
            s0.z = acc[u][2].x + rpbh[(size_t)rowv[2] * NTOK + j0] + (rvr[2] != rj0 ? -100.f : 0.f);
            s0.w = acc[u][3].x + rpbh[(size_t)rowv[3] * NTOK + j0] + (rvr[3] != rj0 ? -100.f : 0.f);
            *(float4*)(sc + j0 * 4) = s0;
            if (j1 < NTOK) {
                int rj1 = rv[j1];
                float4 s1;
                s1.x = acc[u][0].y + rpbh[(size_t)rowv[0] * NTOK + j1] + (rvr[0] != rj1 ? -100.f : 0.f);
                s1.y = acc[u][1].y + rpbh[(size_t)rowv[1] * NTOK + j1] + (rvr[1] != rj1 ? -100.f : 0.f);
                s1.z = acc[u][2].y + rpbh[(size_t)rowv[2] * NTOK + j1] + (rvr[2] != rj1 ? -100.f : 0.f);
                s1.w = acc[u][3].y + rpbh[(size_t)rowv[3] * NTOK + j1] + (rvr[3] != rj1 ? -100.f : 0.f);
                *(float4*)(sc + j1 * 4) = s1;
            }
        }
        __syncwarp();

        float4 mx = make_float4(-1e30f, -1e30f, -1e30f, -1e30f);
        for (int jt = 0; jt < 11; jt++) {
            int j = jt * 32 + lane;
            if (j < NTOK) {
                float4 s4 = *(const float4*)(sc + j * 4);
                mx.x = fmaxf(mx.x, s4.x); mx.y = fmaxf(mx.y, s4.y);
                mx.z = fmaxf(mx.z, s4.z); mx.w = fmaxf(mx.w, s4.w);
            }
        }
        #pragma unroll
        for (int o = 16; o; o >>= 1) {
            mx.x = fmaxf(mx.x, __shfl_xor_sync(~0u, mx.x, o));
            mx.y = fmaxf(mx.y, __shfl_xor_sync(~0u, mx.y, o));
            mx.z = fmaxf(mx.z, __shfl_xor_sync(~0u, mx.z, o));
            mx.w = fmaxf(mx.w, __shfl_xor_sync(~0u, mx.w, o));
        }
        float4 sm = make_float4(0.f, 0.f, 0.f, 0.f);
        for (int jt = 0; jt < 11; jt++) {
            int j = jt * 32 + lane;
            if (j < NTOK) {
                float4 s4 = *(const float4*)(sc + j * 4);
                s4.x = __expf(s4.x - mx.x); s4.y = __expf(s4.y - mx.y);
                s4.z = __expf(s4.z - mx.z); s4.w = __expf(s4.w - mx.w);
                *(float4*)(sc + j * 4) = s4;
                sm.x += s4.x; sm.y += s4.y; sm.z += s4.z; sm.w += s4.w;
            }
        }
        #pragma unroll
        for (int o = 16; o; o >>= 1) {
            sm.x += __shfl_xor_sync(~0u, sm.x, o); sm.y += __shfl_xor_sync(~0u, sm.y, o);
            sm.z += __shfl_xor_sync(~0u, sm.z, o); sm.w += __shfl_xor_sync(~0u, sm.w, o);
        }
        __syncwarp();

        float o0 = 0, o1 = 0, o2 = 0, o3 = 0;
        #pragma unroll 7
        for (int j = 0; j < NTOK; j++) {
            float4 p4 = *(const float4*)(sc + j * 4);
            float vv = vs[j * 32 + lane];
            o0 = fmaf(p4.x, vv, o0); o1 = fmaf(p4.y, vv, o1);
            o2 = fmaf(p4.z, vv, o2); o3 = fmaf(p4.w, vv, o3);
        }
        float oo[4] = {o0 / sm.x, o1 / sm.y, o2 / sm.z, o3 / sm.w};
        for (int r = 0; r < nr; r++)
            d_attn[(size_t)outl[r] * CDIM + h * 32 + lane] = oo[r];
    }
}

// ---------------- LN + residual ----------------
__global__ void __launch_bounds__(256) ln_res_kernel(const float* __restrict__ inp,
                                                     const float* __restrict__ res,
                                                     const float* __restrict__ g,
                                                     const float* __restrict__ bb,
                                                     float* __restrict__ out) {
    int row = blockIdx.x * 8 + (threadIdx.x >> 5);
    int lane = threadIdx.x & 31;
    const float* p = inp + (size_t)row * CDIM;
    float v[6]; float s = 0, s2 = 0;
    #pragma unroll
    for (int i = 0; i < 6; i++) {
        float x = p[lane + 32 * i];
        v[i] = x; s += x; s2 = fmaf(x, x, s2);
    }
    #pragma unroll
    for (int o = 16; o; o >>= 1) {
        s += __shfl_xor_sync(~0u, s, o); s2 += __shfl_xor_sync(~0u, s2, o);
    }
    float mean = s * (1.0f / 192.0f);
    float rstd = rsqrtf(s2 * (1.0f / 192.0f) - mean * mean + 1e-5f);
    const float* rr = res + (size_t)row * CDIM;
    float* oo = out + (size_t)row * CDIM;
    #pragma unroll
    for (int i = 0; i < 6; i++) {
        int c = lane + 32 * i;
        oo[c] = rr[c] + (v[i] - mean) * rstd * g[c] + bb[c];
    }
}

extern "C" void kernel_launch(void* const* d_in, const int* in_sizes, int n_in,
                              void* d_out, int out_size) {
    const float* x      = (const float*)d_in[0];
    const float* qkv_w  = (const float*)d_in[1];
    const float* q_bias = (const float*)d_in[2];
    const float* v_bias = (const float*)d_in[3];
    const float* lscale = (const float*)d_in[4];
    const float* cpb_w1 = (const float*)d_in[5];
    const float* cpb_b1 = (const float*)d_in[6];
    const float* cpb_w2 = (const float*)d_in[7];
    const float* proj_w = (const float*)d_in[8];
    const float* proj_b = (const float*)d_in[9];
    const float* n1g    = (const float*)d_in[10];
    const float* n1b    = (const float*)d_in[11];
    const float* fc1_w  = (const float*)d_in[12];
    const float* fc1_b  = (const float*)d_in[13];
    const float* fc2_w  = (const float*)d_in[14];
    const float* fc2_b  = (const float*)d_in[15];
    const float* n2g    = (const float*)d_in[16];
    const float* n2b    = (const float*)d_in[17];
    float* out = (float*)d_out;

    void *p_attn, *p_tmp, *p_x1, *p_hid;
    cudaGetSymbolAddress(&p_attn, d_attn);
    cudaGetSymbolAddress(&p_tmp, d_tmp);
    cudaGetSymbolAddress(&p_x1, d_x1);
    cudaGetSymbolAddress(&p_hid, d_hid);

    cudaFuncSetAttribute(attn_kernel, cudaFuncAttributeMaxDynamicSharedMemorySize, 109424);

    cpb_kernel<<<275, 256>>>(cpb_w1, cpb_b1, cpb_w2);
    rpb_kernel<<<2758, 256>>>();

    gemm_mma<true, 2><<<dim3(9, 343), 256>>>(x, qkv_w, nullptr, nullptr, 192, 576, 6, q_bias, v_bias);
    attn_kernel<<<768, 224, 109424>>>(lscale);
    gemm_mma<false, 0><<<dim3(3, 343), 256>>>((const float*)p_attn, proj_w, proj_b,
                                              (float*)p_tmp, 192, 192, 6, nullptr, nullptr);
    ln_res_kernel<<<5488, 256>>>((const float*)p_tmp, x, n1g, n1b, (float*)p_x1);
    gemm_mma<false, 1><<<dim3(12, 343), 256>>>((const float*)p_x1, fc1_w, fc1_b,
                                               (float*)p_hid, 192, 768, 6, nullptr, nullptr);
    gemm_mma<false, 0><<<dim3(3, 343), 256>>>((const float*)p_hid, fc2_w, fc2_b,
                                              (float*)p_tmp, 768, 192, 24, nullptr, nullptr);
    ln_res_kernel<<<5488, 256>>>((const float*)p_tmp, (const float*)p_x1, n2g, n2b, out);
}

// round 5
// speedup vs baseline: 2.5379x; 1.2737x over previous
#include <cuda_runtime.h>
#include <cuda_bf16.h>
#include <cuda_fp16.h>
#include <math.h>
#include <stdint.h>

#define NTOK 343
#define CDIM 192
#define LTOK 21952
#define QS_STR 40
#define VT_STR 362

__device__ float d_q[8429568];
__device__ float d_k[8429568];
__device__ float d_v[8429568];
__device__ float d_hb[2197 * 6];
__device__ float d_rpb[6 * 343 * 344];
__device__ float d_attn[43904 * 192];
__device__ float d_tmp[43904 * 192];
__device__ float d_x1[43904 * 192];
__device__ float d_hid[43904 * 768];

__device__ __forceinline__ int regcls(int c) { return c < 21 ? 0 : (c < 25 ? 1 : 2); }
__device__ __forceinline__ float cpb_coord(int i) {
    float x = (float)(i - 6) * (8.0f / 6.0f);
    return copysignf(log2f(fabsf(x) + 1.0f) * (1.0f / 3.0f), x);
}
__device__ __forceinline__ int gather_row(int m) {
    int b_ = m / 343;  int n = m - b_ * 343;
    int b  = b_ >> 6;  int widx = b_ & 63;
    int th = n / 49;   int rem = n - th * 49;
    int tw = rem / 7;  int td = rem - tw * 7;
    int hh = ((widx >> 4) * 7 + th + 3) % 28;
    int wc = (((widx >> 2) & 3) * 7 + tw + 3) % 28;
    int dc = ((widx & 3) * 7 + td + 3) % 28;
    return b * LTOK + (hh * 28 + wc) * 28 + dc;
}

__device__ __forceinline__ void mma16816(float* d, const uint32_t* a, const uint32_t* b) {
    asm volatile(
        "mma.sync.aligned.m16n8k16.row.col.f32.bf16.bf16.f32 "
        "{%0,%1,%2,%3}, {%4,%5,%6,%7}, {%8,%9}, {%0,%1,%2,%3};"
        : "+f"(d[0]), "+f"(d[1]), "+f"(d[2]), "+f"(d[3])
        : "r"(a[0]), "r"(a[1]), "r"(a[2]), "r"(a[3]), "r"(b[0]), "r"(b[1]));
}
__device__ __forceinline__ void mma_f16(float* d, const uint32_t* a, const uint32_t* b) {
    asm volatile(
        "mma.sync.aligned.m16n8k16.row.col.f32.f16.f16.f32 "
        "{%0,%1,%2,%3}, {%4,%5,%6,%7}, {%8,%9}, {%0,%1,%2,%3};"
        : "+f"(d[0]), "+f"(d[1]), "+f"(d[2]), "+f"(d[3])
        : "r"(a[0]), "r"(a[1]), "r"(a[2]), "r"(a[3]), "r"(b[0]), "r"(b[1]));
}

// ---------------- CPB MLP ----------------
__global__ void __launch_bounds__(256) cpb_kernel(const float* __restrict__ w1,
                                                  const float* __restrict__ b1,
                                                  const float* __restrict__ w2) {
    int row = blockIdx.x * 8 + (threadIdx.x >> 5);
    if (row >= 2197) return;
    int lane = threadIdx.x & 31;
    int dh = row / 169; int rem = row - dh * 169;
    int dw = rem / 13;  int dd = rem - dw * 13;
    float c0 = cpb_coord(dh), c1 = cpb_coord(dw), c2 = cpb_coord(dd);
    float a0 = 0, a1 = 0, a2 = 0, a3 = 0, a4 = 0, a5 = 0;
    for (int i = lane; i < 512; i += 32) {
        float hv = c0 * w1[i * 3] + c1 * w1[i * 3 + 1] + c2 * w1[i * 3 + 2] + b1[i];
        hv = fmaxf(hv, 0.0f);
        a0 = fmaf(hv, w2[i], a0);        a1 = fmaf(hv, w2[512 + i], a1);
        a2 = fmaf(hv, w2[1024 + i], a2); a3 = fmaf(hv, w2[1536 + i], a3);
        a4 = fmaf(hv, w2[2048 + i], a4); a5 = fmaf(hv, w2[2560 + i], a5);
    }
    #pragma unroll
    for (int o = 16; o; o >>= 1) {
        a0 += __shfl_xor_sync(~0u, a0, o); a1 += __shfl_xor_sync(~0u, a1, o);
        a2 += __shfl_xor_sync(~0u, a2, o); a3 += __shfl_xor_sync(~0u, a3, o);
        a4 += __shfl_xor_sync(~0u, a4, o); a5 += __shfl_xor_sync(~0u, a5, o);
    }
    if (lane == 0) {
        d_hb[row * 6 + 0] = a0; d_hb[row * 6 + 1] = a1; d_hb[row * 6 + 2] = a2;
        d_hb[row * 6 + 3] = a3; d_hb[row * 6 + 4] = a4; d_hb[row * 6 + 5] = a5;
    }
}

__global__ void __launch_bounds__(256) rpb_kernel() {
    int g = blockIdx.x * 256 + threadIdx.x;
    if (g >= 6 * 343 * 343) return;
    int h = g / (343 * 343); int rem = g - h * 343 * 343;
    int i = rem / 343; int j = rem - i * 343;
    int ih = i / 49, iw = (i / 7) % 7, id = i % 7;
    int jh = j / 49, jw = (j / 7) % 7, jd = j % 7;
    int idx = (ih - jh + 6) * 169 + (iw - jw + 6) * 13 + (id - jd + 6);
    d_rpb[(size_t)h * 343 * 344 + i * 344 + j] = 16.0f / (1.0f + __expf(-d_hb[idx * 6 + h]));
}

// ---------------- HMMA GEMM (bf16 split precision), tile 128x64 ----------------
template <bool GATHER, int EPI>
__global__ void __launch_bounds__(256) gemm_mma(
    const float* __restrict__ A, const float* __restrict__ W,
    const float* __restrict__ bias, float* __restrict__ C,
    int Ktot, int Nout, int nchunks,
    const float* __restrict__ qb, const float* __restrict__ vb)
{
    __shared__ __nv_bfloat16 Ah[128][40], Al[128][40], Bh[64][40], Bl[64][40];
    int t = threadIdx.x, lane = t & 31, wid = t >> 5;
    int n0 = blockIdx.x * 64, m0 = blockIdx.y * 128;
    int wm = wid >> 1, wn = wid & 1;

    float acc[2][4][4];
    #pragma unroll
    for (int mf = 0; mf < 2; mf++)
        #pragma unroll
        for (int nf = 0; nf < 4; nf++)
            #pragma unroll
            for (int e = 0; e < 4; e++) acc[mf][nf][e] = 0.0f;

    const float* arow[4];
    #pragma unroll
    for (int it = 0; it < 4; it++) {
        int row = (t + 256 * it) >> 3;
        int grow = GATHER ? gather_row(m0 + row) : (m0 + row);
        arow[it] = A + (size_t)grow * Ktot;
    }
    const float* brow[2];
    #pragma unroll
    for (int it = 0; it < 2; it++) {
        int row = (t + 256 * it) >> 3;
        brow[it] = W + (size_t)(n0 + row) * Ktot;
    }

    int rA = wm * 32 + (lane >> 2);
    int kA = (lane & 3) * 2;
    int cB = wn * 32 + (lane >> 2);

    for (int kc = 0; kc < nchunks; kc++) {
        #pragma unroll
        for (int it = 0; it < 4; it++) {
            int i = t + 256 * it;
            int row = i >> 3, c4 = i & 7;
            float4 v = *(const float4*)(arow[it] + kc * 32 + c4 * 4);
            __nv_bfloat16 h0 = __float2bfloat16_rn(v.x), h1 = __float2bfloat16_rn(v.y);
            __nv_bfloat16 h2 = __float2bfloat16_rn(v.z), h3 = __float2bfloat16_rn(v.w);
            *(__nv_bfloat162*)&Ah[row][c4 * 4]     = __halves2bfloat162(h0, h1);
            *(__nv_bfloat162*)&Ah[row][c4 * 4 + 2] = __halves2bfloat162(h2, h3);
            *(__nv_bfloat162*)&Al[row][c4 * 4]     = __floats2bfloat162_rn(v.x - __bfloat162float(h0), v.y - __bfloat162float(h1));
            *(__nv_bfloat162*)&Al[row][c4 * 4 + 2] = __floats2bfloat162_rn(v.z - __bfloat162float(h2), v.w - __bfloat162float(h3));
        }
        #pragma unroll
        for (int it = 0; it < 2; it++) {
            int i = t + 256 * it;
            int row = i >> 3, c4 = i & 7;
            float4 v = *(const float4*)(brow[it] + kc * 32 + c4 * 4);
            __nv_bfloat16 h0 = __float2bfloat16_rn(v.x), h1 = __float2bfloat16_rn(v.y);
            __nv_bfloat16 h2 = __float2bfloat16_rn(v.z), h3 = __float2bfloat16_rn(v.w);
            *(__nv_bfloat162*)&Bh[row][c4 * 4]     = __halves2bfloat162(h0, h1);
            *(__nv_bfloat162*)&Bh[row][c4 * 4 + 2] = __halves2bfloat162(h2, h3);
            *(__nv_bfloat162*)&Bl[row][c4 * 4]     = __floats2bfloat162_rn(v.x - __bfloat162float(h0), v.y - __bfloat162float(h1));
            *(__nv_bfloat162*)&Bl[row][c4 * 4 + 2] = __floats2bfloat162_rn(v.z - __bfloat162float(h2), v.w - __bfloat162float(h3));
        }
        __syncthreads();

        #pragma unroll
        for (int ks = 0; ks < 2; ks++) {
            int kb = ks * 16 + kA;
            uint32_t ah[2][4], al[2][4];
            #pragma unroll
            for (int mf = 0; mf < 2; mf++) {
                int r = rA + mf * 16;
                ah[mf][0] = *(const uint32_t*)&Ah[r][kb];
                ah[mf][1] = *(const uint32_t*)&Ah[r + 8][kb];
                ah[mf][2] = *(const uint32_t*)&Ah[r][kb + 8];
                ah[mf][3] = *(const uint32_t*)&Ah[r + 8][kb + 8];
                al[mf][0] = *(const uint32_t*)&Al[r][kb];
                al[mf][1] = *(const uint32_t*)&Al[r + 8][kb];
                al[mf][2] = *(const uint32_t*)&Al[r][kb + 8];
                al[mf][3] = *(const uint32_t*)&Al[r + 8][kb + 8];
            }
            #pragma unroll
            for (int nf = 0; nf < 4; nf++) {
                int c = cB + nf * 8;
                uint32_t bh[2], bl[2];
                bh[0] = *(const uint32_t*)&Bh[c][kb];
                bh[1] = *(const uint32_t*)&Bh[c][kb + 8];
                bl[0] = *(const uint32_t*)&Bl[c][kb];
                bl[1] = *(const uint32_t*)&Bl[c][kb + 8];
                #pragma unroll
                for (int mf = 0; mf < 2; mf++) {
                    mma16816(acc[mf][nf], ah[mf], bh);
                    mma16816(acc[mf][nf], al[mf], bh);
                    mma16816(acc[mf][nf], ah[mf], bl);
                }
            }
        }
        __syncthreads();
    }

    int rbase = m0 + wm * 32 + (lane >> 2);
    int cbase = n0 + wn * 32 + (lane & 3) * 2;
    int sec = 0;
    if (EPI == 2) sec = n0 / 192;
    #pragma unroll
    for (int mf = 0; mf < 2; mf++) {
        #pragma unroll
        for (int half = 0; half < 2; half++) {
            int row = rbase + mf * 16 + half * 8;
            #pragma unroll
            for (int nf = 0; nf < 4; nf++) {
                int col = cbase + nf * 8;
                float v0 = acc[mf][nf][half * 2 + 0];
                float v1 = acc[mf][nf][half * 2 + 1];
                if (EPI == 2) {
                    int cc = col - sec * 192;
                    int head = cc >> 5, dd = cc & 31;
                    int b_ = row / 343; int n = row - b_ * 343;
                    size_t dst = ((size_t)(b_ * 6 + head) * 343 + n) * 32 + dd;
                    float* dp = (sec == 0) ? d_q : (sec == 1 ? d_k : d_v);
                    if (sec == 0) { v0 += qb[cc]; v1 += qb[cc + 1]; }
                    else if (sec == 2) { v0 += vb[cc]; v1 += vb[cc + 1]; }
                    *(float2*)(dp + dst) = make_float2(v0, v1);
                } else {
                    v0 += bias[col]; v1 += bias[col + 1];
                    if (EPI == 1) {
                        v0 = 0.5f * v0 * (1.0f + erff(v0 * 0.70710678f));
                        v1 = 0.5f * v1 * (1.0f + erff(v1 * 0.70710678f));
                    }
                    *(float2*)&C[(size_t)row * Nout + col] = make_float2(v0, v1);
                }
            }
        }
    }
}

// ---------------- fp16 mma attention, FA2-style ----------------
// smem: qs h[352][40]@0, ks h[352][40]@28160, vts h[32][362]@56320, rv int[352]@79488
__global__ void __launch_bounds__(128, 2) attn_mma(const float* __restrict__ logit_scale) {
    extern __shared__ char smraw[];
    __half* qs  = (__half*)smraw;
    __half* ks  = (__half*)(smraw + 28160);
    __half* vts = (__half*)(smraw + 56320);
    int*    rv  = (int*)(smraw + 79488);

    int bh = blockIdx.x;
    int b_ = bh / 6, h = bh - b_ * 6;
    int t = threadIdx.x, wid = t >> 5, lane = t & 31;
    size_t base = (size_t)(b_ * 6 + h) * 343 * 32;
    float scale = __expf(fminf(logit_scale[h], 4.6051702f));

    for (int j = wid; j < 343; j += 4) {
        float kv = d_k[base + j * 32 + lane];
        float ss = kv * kv;
        #pragma unroll
        for (int o = 16; o; o >>= 1) ss += __shfl_xor_sync(~0u, ss, o);
        ks[j * QS_STR + lane] = __float2half_rn(kv * (1.0f / fmaxf(sqrtf(ss), 1e-12f)));
        vts[lane * VT_STR + j] = __float2half_rn(d_v[base + j * 32 + lane]);
        float qv = d_q[base + j * 32 + lane];
        float qq = qv * qv;
        #pragma unroll
        for (int o = 16; o; o >>= 1) qq += __shfl_xor_sync(~0u, qq, o);
        qs[j * QS_STR + lane] = __float2half_rn(qv * (1.0f / fmaxf(sqrtf(qq), 1e-12f)) * scale);
    }
    if (t < 32) {
        #pragma unroll
        for (int j = 343; j < 352; j++) {
            ks[j * QS_STR + t] = __float2half_rn(0.f);
            qs[j * QS_STR + t] = __float2half_rn(0.f);
            vts[t * VT_STR + j] = __float2half_rn(0.f);
        }
    }
    int widx = b_ & 63;
    int wh = widx >> 4, ww = (widx >> 2) & 3, wd = widx & 3;
    for (int n = t; n < 352; n += 128) {
        if (n < 343) {
            int th = n / 49; int rem = n - th * 49;
            int tw = rem / 7; int td = rem - tw * 7;
            rv[n] = regcls(wh * 7 + th) * 9 + regcls(ww * 7 + tw) * 3 + regcls(wd * 7 + td);
        } else rv[n] = -1;
    }
    __syncthreads();

    int b = b_ >> 6;
    const float* rpbh = d_rpb + (size_t)h * 343 * 344;
    int lq = lane >> 2;          // 0..7
    int lr2 = (lane & 3) * 2;    // 0,2,4,6

    for (int tile = wid; tile < 22; tile += 4) {
        int r0 = tile * 16 + lq;
        int r1 = r0 + 8;
        uint32_t aq[2][4];
        #pragma unroll
        for (int kf = 0; kf < 2; kf++) {
            int kb = kf * 16 + lr2;
            aq[kf][0] = *(const uint32_t*)&qs[r0 * QS_STR + kb];
            aq[kf][1] = *(const uint32_t*)&qs[r1 * QS_STR + kb];
            aq[kf][2] = *(const uint32_t*)&qs[r0 * QS_STR + kb + 8];
            aq[kf][3] = *(const uint32_t*)&qs[r1 * QS_STR + kb + 8];
        }
        int r0c = r0 < 343 ? r0 : 342, r1c = r1 < 343 ? r1 : 342;
        int rv0 = rv[r0c], rv1 = rv[r1c];
        const float* rpb0 = rpbh + (size_t)r0c * 344;
        const float* rpb1 = rpbh + (size_t)r1c * 344;

        float m0 = -1e30f, m1 = -1e30f, l0 = 0.f, l1 = 0.f;
        float out[4][4];
        #pragma unroll
        for (int nfv = 0; nfv < 4; nfv++)
            #pragma unroll
            for (int e = 0; e < 4; e++) out[nfv][e] = 0.f;

        for (int half = 0; half < 2; half++) {
            float acc[22][4];
            #pragma unroll
            for (int nf = 0; nf < 22; nf++)
                #pragma unroll
                for (int e = 0; e < 4; e++) acc[nf][e] = 0.f;

            #pragma unroll
            for (int nf = 0; nf < 22; nf++) {
                int cb = half * 176 + nf * 8 + lq;
                uint32_t b0[2], b1[2];
                b0[0] = *(const uint32_t*)&ks[cb * QS_STR + lr2];
                b0[1] = *(const uint32_t*)&ks[cb * QS_STR + lr2 + 8];
                b1[0] = *(const uint32_t*)&ks[cb * QS_STR + 16 + lr2];
                b1[1] = *(const uint32_t*)&ks[cb * QS_STR + 16 + lr2 + 8];
                mma_f16(acc[nf], aq[0], b0);
                mma_f16(acc[nf], aq[1], b1);
            }
            // bias + mask
            #pragma unroll
            for (int nf = 0; nf < 22; nf++) {
                int c = half * 176 + nf * 8 + lr2;
                if (c < 343) {
                    float2 rp0 = *(const float2*)(rpb0 + c);
                    float2 rp1 = *(const float2*)(rpb1 + c);
                    int rc0 = rv[c];
                    acc[nf][0] += rp0.x + (rc0 == rv0 ? 0.f : -100.f);
                    acc[nf][2] += rp1.x + (rc0 == rv1 ? 0.f : -100.f);
                    if (c + 1 < 343) {
                        int rc1 = rv[c + 1];
                        acc[nf][1] += rp0.y + (rc1 == rv0 ? 0.f : -100.f);
                        acc[nf][3] += rp1.y + (rc1 == rv1 ? 0.f : -100.f);
                    } else { acc[nf][1] = -1e30f; acc[nf][3] = -1e30f; }
                } else {
                    acc[nf][0] = acc[nf][1] = acc[nf][2] = acc[nf][3] = -1e30f;
                }
            }
            // row max
            float h0 = -1e30f, h1 = -1e30f;
            #pragma unroll
            for (int nf = 0; nf < 22; nf++) {
                h0 = fmaxf(h0, fmaxf(acc[nf][0], acc[nf][1]));
                h1 = fmaxf(h1, fmaxf(acc[nf][2], acc[nf][3]));
            }
            h0 = fmaxf(h0, __shfl_xor_sync(~0u, h0, 1));
            h0 = fmaxf(h0, __shfl_xor_sync(~0u, h0, 2));
            h1 = fmaxf(h1, __shfl_xor_sync(~0u, h1, 1));
            h1 = fmaxf(h1, __shfl_xor_sync(~0u, h1, 2));
            float mn0 = fmaxf(m0, h0), mn1 = fmaxf(m1, h1);
            float sc0 = __expf(m0 - mn0), sc1 = __expf(m1 - mn1);
            m0 = mn0; m1 = mn1;
            l0 *= sc0; l1 *= sc1;
            #pragma unroll
            for (int nfv = 0; nfv < 4; nfv++) {
                out[nfv][0] *= sc0; out[nfv][1] *= sc0;
                out[nfv][2] *= sc1; out[nfv][3] *= sc1;
            }
            uint32_t pp0[22], pp1[22];
            float s0 = 0.f, s1 = 0.f;
            #pragma unroll
            for (int nf = 0; nf < 22; nf++) {
                float e0 = __expf(acc[nf][0] - m0), e1 = __expf(acc[nf][1] - m0);
                float e2 = __expf(acc[nf][2] - m1), e3 = __expf(acc[nf][3] - m1);
                s0 += e0 + e1; s1 += e2 + e3;
                __half2 p0 = __floats2half2_rn(e0, e1);
                __half2 p1 = __floats2half2_rn(e2, e3);
                pp0[nf] = *(uint32_t*)&p0;
                pp1[nf] = *(uint32_t*)&p1;
            }
            l0 += s0; l1 += s1;
            // PV
            #pragma unroll
            for (int kf = 0; kf < 11; kf++) {
                uint32_t ap[4] = { pp0[2 * kf], pp1[2 * kf], pp0[2 * kf + 1], pp1[2 * kf + 1] };
                int kk = half * 176 + kf * 16 + lr2;
                #pragma unroll
                for (int nfv = 0; nfv < 4; nfv++) {
                    const __half* vb = &vts[(nfv * 8 + lq) * VT_STR + kk];
                    uint32_t bb[2] = { *(const uint32_t*)vb, *(const uint32_t*)(vb + 8) };
                    mma_f16(out[nfv], ap, bb);
                }
            }
        }
        l0 += __shfl_xor_sync(~0u, l0, 1); l0 += __shfl_xor_sync(~0u, l0, 2);
        l1 += __shfl_xor_sync(~0u, l1, 1); l1 += __shfl_xor_sync(~0u, l1, 2);
        float inv0 = 1.0f / l0, inv1 = 1.0f / l1;

        if (r0 < 343) {
            int th = r0 / 49, rem = r0 - th * 49, tw = rem / 7, td = rem - tw * 7;
            int o0 = b * LTOK + (((wh * 7 + th + 3) % 28) * 28 + ((ww * 7 + tw + 3) % 28)) * 28 + ((wd * 7 + td + 3) % 28);
            float* dp = d_attn + (size_t)o0 * CDIM + h * 32 + lr2;
            #pragma unroll
            for (int nfv = 0; nfv < 4; nfv++)
                *(float2*)(dp + nfv * 8) = make_float2(out[nfv][0] * inv0, out[nfv][1] * inv0);
        }
        if (r1 < 343) {
            int th = r1 / 49, rem = r1 - th * 49, tw = rem / 7, td = rem - tw * 7;
            int o1 = b * LTOK + (((wh * 7 + th + 3) % 28) * 28 + ((ww * 7 + tw + 3) % 28)) * 28 + ((wd * 7 + td + 3) % 28);
            float* dp = d_attn + (size_t)o1 * CDIM + h * 32 + lr2;
            #pragma unroll
            for (int nfv = 0; nfv < 4; nfv++)
                *(float2*)(dp + nfv * 8) = make_float2(out[nfv][2] * inv1, out[nfv][3] * inv1);
        }
    }
}

// ---------------- LN + residual ----------------
__global__ void __launch_bounds__(256) ln_res_kernel(const float* __restrict__ inp,
                                                     const float* __restrict__ res,
                                                     const float* __restrict__ g,
                                                     const float* __restrict__ bb,
                                                     float* __restrict__ out) {
    int row = blockIdx.x * 8 + (threadIdx.x >> 5);
    int lane = threadIdx.x & 31;
    const float* p = inp + (size_t)row * CDIM;
    float v[6]; float s = 0, s2 = 0;
    #pragma unroll
    for (int i = 0; i < 6; i++) {
        float x = p[lane + 32 * i];
        v[i] = x; s += x; s2 = fmaf(x, x, s2);
    }
    #pragma unroll
    for (int o = 16; o; o >>= 1) {
        s += __shfl_xor_sync(~0u, s, o); s2 += __shfl_xor_sync(~0u, s2, o);
    }
    float mean = s * (1.0f / 192.0f);
    float rstd = rsqrtf(s2 * (1.0f / 192.0f) - mean * mean + 1e-5f);
    const float* rr = res + (size_t)row * CDIM;
    float* oo = out + (size_t)row * CDIM;
    #pragma unroll
    for (int i = 0; i < 6; i++) {
        int c = lane + 32 * i;
        oo[c] = rr[c] + (v[i] - mean) * rstd * g[c] + bb[c];
    }
}

extern "C" void kernel_launch(void* const* d_in, const int* in_sizes, int n_in,
                              void* d_out, int out_size) {
    const float* x      = (const float*)d_in[0];
    const float* qkv_w  = (const float*)d_in[1];
    const float* q_bias = (const float*)d_in[2];
    const float* v_bias = (const float*)d_in[3];
    const float* lscale = (const float*)d_in[4];
    const float* cpb_w1 = (const float*)d_in[5];
    const float* cpb_b1 = (const float*)d_in[6];
    const float* cpb_w2 = (const float*)d_in[7];
    const float* proj_w = (const float*)d_in[8];
    const float* proj_b = (const float*)d_in[9];
    const float* n1g    = (const float*)d_in[10];
    const float* n1b    = (const float*)d_in[11];
    const float* fc1_w  = (const float*)d_in[12];
    const float* fc1_b  = (const float*)d_in[13];
    const float* fc2_w  = (const float*)d_in[14];
    const float* fc2_b  = (const float*)d_in[15];
    const float* n2g    = (const float*)d_in[16];
    const float* n2b    = (const float*)d_in[17];
    float* out = (float*)d_out;

    void *p_attn, *p_tmp, *p_x1, *p_hid;
    cudaGetSymbolAddress(&p_attn, d_attn);
    cudaGetSymbolAddress(&p_tmp, d_tmp);
    cudaGetSymbolAddress(&p_x1, d_x1);
    cudaGetSymbolAddress(&p_hid, d_hid);

    cudaFuncSetAttribute(attn_mma, cudaFuncAttributeMaxDynamicSharedMemorySize, 80896);

    cpb_kernel<<<275, 256>>>(cpb_w1, cpb_b1, cpb_w2);
    rpb_kernel<<<2758, 256>>>();

    gemm_mma<true, 2><<<dim3(9, 343), 256>>>(x, qkv_w, nullptr, nullptr, 192, 576, 6, q_bias, v_bias);
    attn_mma<<<768, 128, 80896>>>(lscale);
    gemm_mma<false, 0><<<dim3(3, 343), 256>>>((const float*)p_attn, proj_w, proj_b,
                                              (float*)p_tmp, 192, 192, 6, nullptr, nullptr);
    ln_res_kernel<<<5488, 256>>>((const float*)p_tmp, x, n1g, n1b, (float*)p_x1);
    gemm_mma<false, 1><<<dim3(12, 343), 256>>>((const float*)p_x1, fc1_w, fc1_b,
                                               (float*)p_hid, 192, 768, 6, nullptr, nullptr);
    gemm_mma<false, 0><<<dim3(3, 343), 256>>>((const float*)p_hid, fc2_w, fc2_b,
                                              (float*)p_tmp, 768, 192, 24, nullptr, nullptr);
    ln_res_kernel<<<5488, 256>>>((const float*)p_tmp, (const float*)p_x1, n2g, n2b, out);
}

// round 6
// speedup vs baseline: 2.8760x; 1.1332x over previous
#include <cuda_runtime.h>
#include <cuda_bf16.h>
#include <cuda_fp16.h>
#include <math.h>
#include <stdint.h>

#define NTOK 343
#define CDIM 192
#define LTOK 21952
#define KS_STR 40
#define VT_STR 354
#define RPB_STR 352

__device__ float d_q[8429568];
__device__ float d_k[8429568];
__device__ float d_v[8429568];
__device__ float d_hb[2197 * 6];
__device__ float d_rpbm[8 * 6 * 343 * RPB_STR];   // masked bias per window-type
__device__ float d_attn[43904 * 192];
__device__ float d_tmp[43904 * 192];
__device__ float d_x1[43904 * 192];
__device__ float d_hid[43904 * 768];

__device__ __forceinline__ float cpb_coord(int i) {
    float x = (float)(i - 6) * (8.0f / 6.0f);
    return copysignf(log2f(fabsf(x) + 1.0f) * (1.0f / 3.0f), x);
}
__device__ __forceinline__ int gather_row(int m) {
    int b_ = m / 343;  int n = m - b_ * 343;
    int b  = b_ >> 6;  int widx = b_ & 63;
    int th = n / 49;   int rem = n - th * 49;
    int tw = rem / 7;  int td = rem - tw * 7;
    int hh = ((widx >> 4) * 7 + th + 3) % 28;
    int wc = (((widx >> 2) & 3) * 7 + tw + 3) % 28;
    int dc = ((widx & 3) * 7 + td + 3) % 28;
    return b * LTOK + (hh * 28 + wc) * 28 + dc;
}

__device__ __forceinline__ void mma16816(float* d, const uint32_t* a, const uint32_t* b) {
    asm volatile(
        "mma.sync.aligned.m16n8k16.row.col.f32.bf16.bf16.f32 "
        "{%0,%1,%2,%3}, {%4,%5,%6,%7}, {%8,%9}, {%0,%1,%2,%3};"
        : "+f"(d[0]), "+f"(d[1]), "+f"(d[2]), "+f"(d[3])
        : "r"(a[0]), "r"(a[1]), "r"(a[2]), "r"(a[3]), "r"(b[0]), "r"(b[1]));
}
__device__ __forceinline__ void mma_f16(float* d, const uint32_t* a, const uint32_t* b) {
    asm volatile(
        "mma.sync.aligned.m16n8k16.row.col.f32.f16.f16.f32 "
        "{%0,%1,%2,%3}, {%4,%5,%6,%7}, {%8,%9}, {%0,%1,%2,%3};"
        : "+f"(d[0]), "+f"(d[1]), "+f"(d[2]), "+f"(d[3])
        : "r"(a[0]), "r"(a[1]), "r"(a[2]), "r"(a[3]), "r"(b[0]), "r"(b[1]));
}

// ---------------- CPB MLP ----------------
__global__ void __launch_bounds__(256) cpb_kernel(const float* __restrict__ w1,
                                                  const float* __restrict__ b1,
                                                  const float* __restrict__ w2) {
    int row = blockIdx.x * 8 + (threadIdx.x >> 5);
    if (row >= 2197) return;
    int lane = threadIdx.x & 31;
    int dh = row / 169; int rem = row - dh * 169;
    int dw = rem / 13;  int dd = rem - dw * 13;
    float c0 = cpb_coord(dh), c1 = cpb_coord(dw), c2 = cpb_coord(dd);
    float a0 = 0, a1 = 0, a2 = 0, a3 = 0, a4 = 0, a5 = 0;
    for (int i = lane; i < 512; i += 32) {
        float hv = c0 * w1[i * 3] + c1 * w1[i * 3 + 1] + c2 * w1[i * 3 + 2] + b1[i];
        hv = fmaxf(hv, 0.0f);
        a0 = fmaf(hv, w2[i], a0);        a1 = fmaf(hv, w2[512 + i], a1);
        a2 = fmaf(hv, w2[1024 + i], a2); a3 = fmaf(hv, w2[1536 + i], a3);
        a4 = fmaf(hv, w2[2048 + i], a4); a5 = fmaf(hv, w2[2560 + i], a5);
    }
    #pragma unroll
    for (int o = 16; o; o >>= 1) {
        a0 += __shfl_xor_sync(~0u, a0, o); a1 += __shfl_xor_sync(~0u, a1, o);
        a2 += __shfl_xor_sync(~0u, a2, o); a3 += __shfl_xor_sync(~0u, a3, o);
        a4 += __shfl_xor_sync(~0u, a4, o); a5 += __shfl_xor_sync(~0u, a5, o);
    }
    if (lane == 0) {
        d_hb[row * 6 + 0] = a0; d_hb[row * 6 + 1] = a1; d_hb[row * 6 + 2] = a2;
        d_hb[row * 6 + 3] = a3; d_hb[row * 6 + 4] = a4; d_hb[row * 6 + 5] = a5;
    }
}

// ---------------- masked bias table: rpbm[wt][h][i][j] ----------------
__global__ void __launch_bounds__(256) rpbm_kernel() {
    int g = blockIdx.x * 256 + threadIdx.x;
    int j = g % RPB_STR; int rem = g / RPB_STR;
    int i = rem % 343;   rem /= 343;
    int h = rem % 6;     int wt = rem / 6;
    if (wt >= 8) return;
    float val;
    if (j >= 343) {
        val = -30000.0f;
    } else {
        int ih = i / 49, iw = (i / 7) % 7, id = i % 7;
        int jh = j / 49, jw = (j / 7) % 7, jd = j % 7;
        int idx = (ih - jh + 6) * 169 + (iw - jw + 6) * 13 + (id - jd + 6);
        float rpb = 16.0f / (1.0f + __expf(-d_hb[idx * 6 + h]));
        int ci = ((wt & 4) ? (ih < 4 ? 1 : 2) : 0) * 9
               + ((wt & 2) ? (iw < 4 ? 1 : 2) : 0) * 3
               + ((wt & 1) ? (id < 4 ? 1 : 2) : 0);
        int cj = ((wt & 4) ? (jh < 4 ? 1 : 2) : 0) * 9
               + ((wt & 2) ? (jw < 4 ? 1 : 2) : 0) * 3
               + ((wt & 1) ? (jd < 4 ? 1 : 2) : 0);
        val = rpb + (ci == cj ? 0.0f : -100.0f);
    }
    d_rpbm[g] = val;
}

// ---------------- HMMA GEMM (bf16 split precision), tile 128x64 ----------------
template <bool GATHER, int EPI>
__global__ void __launch_bounds__(256) gemm_mma(
    const float* __restrict__ A, const float* __restrict__ W,
    const float* __restrict__ bias, float* __restrict__ C,
    int Ktot, int Nout, int nchunks,
    const float* __restrict__ qb, const float* __restrict__ vb)
{
    __shared__ __nv_bfloat16 Ah[128][40], Al[128][40], Bh[64][40], Bl[64][40];
    int t = threadIdx.x, lane = t & 31, wid = t >> 5;
    int n0 = blockIdx.x * 64, m0 = blockIdx.y * 128;
    int wm = wid >> 1, wn = wid & 1;

    float acc[2][4][4];
    #pragma unroll
    for (int mf = 0; mf < 2; mf++)
        #pragma unroll
        for (int nf = 0; nf < 4; nf++)
            #pragma unroll
            for (int e = 0; e < 4; e++) acc[mf][nf][e] = 0.0f;

    const float* arow[4];
    #pragma unroll
    for (int it = 0; it < 4; it++) {
        int row = (t + 256 * it) >> 3;
        int grow = GATHER ? gather_row(m0 + row) : (m0 + row);
        arow[it] = A + (size_t)grow * Ktot;
    }
    const float* brow[2];
    #pragma unroll
    for (int it = 0; it < 2; it++) {
        int row = (t + 256 * it) >> 3;
        brow[it] = W + (size_t)(n0 + row) * Ktot;
    }

    int rA = wm * 32 + (lane >> 2);
    int kA = (lane & 3) * 2;
    int cB = wn * 32 + (lane >> 2);

    for (int kc = 0; kc < nchunks; kc++) {
        #pragma unroll
        for (int it = 0; it < 4; it++) {
            int i = t + 256 * it;
            int row = i >> 3, c4 = i & 7;
            float4 v = *(const float4*)(arow[it] + kc * 32 + c4 * 4);
            __nv_bfloat16 h0 = __float2bfloat16_rn(v.x), h1 = __float2bfloat16_rn(v.y);
            __nv_bfloat16 h2 = __float2bfloat16_rn(v.z), h3 = __float2bfloat16_rn(v.w);
            *(__nv_bfloat162*)&Ah[row][c4 * 4]     = __halves2bfloat162(h0, h1);
            *(__nv_bfloat162*)&Ah[row][c4 * 4 + 2] = __halves2bfloat162(h2, h3);
            *(__nv_bfloat162*)&Al[row][c4 * 4]     = __floats2bfloat162_rn(v.x - __bfloat162float(h0), v.y - __bfloat162float(h1));
            *(__nv_bfloat162*)&Al[row][c4 * 4 + 2] = __floats2bfloat162_rn(v.z - __bfloat162float(h2), v.w - __bfloat162float(h3));
        }
        #pragma unroll
        for (int it = 0; it < 2; it++) {
            int i = t + 256 * it;
            int row = i >> 3, c4 = i & 7;
            float4 v = *(const float4*)(brow[it] + kc * 32 + c4 * 4);
            __nv_bfloat16 h0 = __float2bfloat16_rn(v.x), h1 = __float2bfloat16_rn(v.y);
            __nv_bfloat16 h2 = __float2bfloat16_rn(v.z), h3 = __float2bfloat16_rn(v.w);
            *(__nv_bfloat162*)&Bh[row][c4 * 4]     = __halves2bfloat162(h0, h1);
            *(__nv_bfloat162*)&Bh[row][c4 * 4 + 2] = __halves2bfloat162(h2, h3);
            *(__nv_bfloat162*)&Bl[row][c4 * 4]     = __floats2bfloat162_rn(v.x - __bfloat162float(h0), v.y - __bfloat162float(h1));
            *(__nv_bfloat162*)&Bl[row][c4 * 4 + 2] = __floats2bfloat162_rn(v.z - __bfloat162float(h2), v.w - __bfloat162float(h3));
        }
        __syncthreads();

        #pragma unroll
        for (int ks = 0; ks < 2; ks++) {
            int kb = ks * 16 + kA;
            uint32_t ah[2][4], al[2][4];
            #pragma unroll
            for (int mf = 0; mf < 2; mf++) {
                int r = rA + mf * 16;
                ah[mf][0] = *(const uint32_t*)&Ah[r][kb];
                ah[mf][1] = *(const uint32_t*)&Ah[r + 8][kb];
                ah[mf][2] = *(const uint32_t*)&Ah[r][kb + 8];
                ah[mf][3] = *(const uint32_t*)&Ah[r + 8][kb + 8];
                al[mf][0] = *(const uint32_t*)&Al[r][kb];
                al[mf][1] = *(const uint32_t*)&Al[r + 8][kb];
                al[mf][2] = *(const uint32_t*)&Al[r][kb + 8];
                al[mf][3] = *(const uint32_t*)&Al[r + 8][kb + 8];
            }
            #pragma unroll
            for (int nf = 0; nf < 4; nf++) {
                int c = cB + nf * 8;
                uint32_t bh[2], bl[2];
                bh[0] = *(const uint32_t*)&Bh[c][kb];
                bh[1] = *(const uint32_t*)&Bh[c][kb + 8];
                bl[0] = *(const uint32_t*)&Bl[c][kb];
                bl[1] = *(const uint32_t*)&Bl[c][kb + 8];
                #pragma unroll
                for (int mf = 0; mf < 2; mf++) {
                    mma16816(acc[mf][nf], ah[mf], bh);
                    mma16816(acc[mf][nf], al[mf], bh);
                    mma16816(acc[mf][nf], ah[mf], bl);
                }
            }
        }
        __syncthreads();
    }

    int rbase = m0 + wm * 32 + (lane >> 2);
    int cbase = n0 + wn * 32 + (lane & 3) * 2;
    int sec = 0;
    if (EPI == 2) sec = n0 / 192;
    #pragma unroll
    for (int mf = 0; mf < 2; mf++) {
        #pragma unroll
        for (int half = 0; half < 2; half++) {
            int row = rbase + mf * 16 + half * 8;
            #pragma unroll
            for (int nf = 0; nf < 4; nf++) {
                int col = cbase + nf * 8;
                float v0 = acc[mf][nf][half * 2 + 0];
                float v1 = acc[mf][nf][half * 2 + 1];
                if (EPI == 2) {
                    int cc = col - sec * 192;
                    int head = cc >> 5, dd = cc & 31;
                    int b_ = row / 343; int n = row - b_ * 343;
                    size_t dst = ((size_t)(b_ * 6 + head) * 343 + n) * 32 + dd;
                    float* dp = (sec == 0) ? d_q : (sec == 1 ? d_k : d_v);
                    if (sec == 0) { v0 += qb[cc]; v1 += qb[cc + 1]; }
                    else if (sec == 2) { v0 += vb[cc]; v1 += vb[cc + 1]; }
                    *(float2*)(dp + dst) = make_float2(v0, v1);
                } else {
                    v0 += bias[col]; v1 += bias[col + 1];
                    if (EPI == 1) {
                        v0 = 0.5f * v0 * (1.0f + erff(v0 * 0.70710678f));
                        v1 = 0.5f * v1 * (1.0f + erff(v1 * 0.70710678f));
                    }
                    *(float2*)&C[(size_t)row * Nout + col] = make_float2(v0, v1);
                }
            }
        }
    }
}

// ---------------- fp16 mma attention, FA2-style, 3 CTAs/SM ----------------
// smem: ks h[352][40]@0 (28160B), vts h[32][354]@28160 (22656B) -> 50816B
__global__ void __launch_bounds__(128, 3) attn_mma(const float* __restrict__ logit_scale) {
    extern __shared__ char smraw[];
    __half* ks  = (__half*)smraw;
    __half* vts = (__half*)(smraw + 28160);

    int bh = blockIdx.x;
    int b_ = bh / 6, h = bh - b_ * 6;
    int t = threadIdx.x, wid = t >> 5, lane = t & 31;
    size_t base = (size_t)(b_ * 6 + h) * 343 * 32;
    float scale = __expf(fminf(logit_scale[h], 4.6051702f));

    for (int j = wid; j < 343; j += 4) {
        float kv = d_k[base + j * 32 + lane];
        float ss = kv * kv;
        #pragma unroll
        for (int o = 16; o; o >>= 1) ss += __shfl_xor_sync(~0u, ss, o);
        ks[j * KS_STR + lane] = __float2half_rn(kv * (1.0f / fmaxf(sqrtf(ss), 1e-12f)));
        vts[lane * VT_STR + j] = __float2half_rn(d_v[base + j * 32 + lane]);
    }
    if (t < 32) {
        #pragma unroll
        for (int j = 343; j < 352; j++) ks[j * KS_STR + t] = __float2half_rn(0.f);
        #pragma unroll
        for (int c = 343; c < 354; c++) vts[t * VT_STR + c] = __float2half_rn(0.f);
    }
    __syncthreads();

    int widx = b_ & 63;
    int wh = widx >> 4, ww = (widx >> 2) & 3, wd = widx & 3;
    int wt = ((wh == 3) << 2) | ((ww == 3) << 1) | (wd == 3);
    const float* rpbase = d_rpbm + (size_t)(wt * 6 + h) * 343 * RPB_STR;
    int b = b_ >> 6;
    int lq = lane >> 2;
    int lr2 = (lane & 3) * 2;

    for (int tile = wid; tile < 22; tile += 4) {
        int r0 = tile * 16 + lq;
        int r1 = r0 + 8;
        int r0c = r0 < 343 ? r0 : 342, r1c = r1 < 343 ? r1 : 342;

        // q fragments straight from gmem + on-the-fly normalization
        const float* q0p = d_q + base + (size_t)r0c * 32;
        const float* q1p = d_q + base + (size_t)r1c * 32;
        float q0v[8], q1v[8], ss0 = 0.f, ss1 = 0.f;
        #pragma unroll
        for (int c = 0; c < 4; c++) {
            float2 a = *(const float2*)(q0p + c * 8 + lr2);
            float2 bq = *(const float2*)(q1p + c * 8 + lr2);
            q0v[2*c] = a.x;  q0v[2*c+1] = a.y;  ss0 += a.x*a.x + a.y*a.y;
            q1v[2*c] = bq.x; q1v[2*c+1] = bq.y; ss1 += bq.x*bq.x + bq.y*bq.y;
        }
        ss0 += __shfl_xor_sync(~0u, ss0, 1); ss0 += __shfl_xor_sync(~0u, ss0, 2);
        ss1 += __shfl_xor_sync(~0u, ss1, 1); ss1 += __shfl_xor_sync(~0u, ss1, 2);
        float inv0 = scale / fmaxf(sqrtf(ss0), 1e-12f);
        float inv1 = scale / fmaxf(sqrtf(ss1), 1e-12f);
        uint32_t aq[2][4];
        #pragma unroll
        for (int kf = 0; kf < 2; kf++) {
            __half2 p;
            p = __floats2half2_rn(q0v[4*kf+0]*inv0, q0v[4*kf+1]*inv0); aq[kf][0] = *(uint32_t*)&p;
            p = __floats2half2_rn(q1v[4*kf+0]*inv1, q1v[4*kf+1]*inv1); aq[kf][1] = *(uint32_t*)&p;
            p = __floats2half2_rn(q0v[4*kf+2]*inv0, q0v[4*kf+3]*inv0); aq[kf][2] = *(uint32_t*)&p;
            p = __floats2half2_rn(q1v[4*kf+2]*inv1, q1v[4*kf+3]*inv1); aq[kf][3] = *(uint32_t*)&p;
        }

        const float* rpb0 = rpbase + (size_t)r0c * RPB_STR;
        const float* rpb1 = rpbase + (size_t)r1c * RPB_STR;

        float m0 = -1e30f, m1 = -1e30f, l0 = 0.f, l1 = 0.f;
        float out[4][4];
        #pragma unroll
        for (int nfv = 0; nfv < 4; nfv++)
            #pragma unroll
            for (int e = 0; e < 4; e++) out[nfv][e] = 0.f;

        #pragma unroll
        for (int half = 0; half < 2; half++) {
            float acc[22][4];
            #pragma unroll
            for (int nf = 0; nf < 22; nf++)
                #pragma unroll
                for (int e = 0; e < 4; e++) acc[nf][e] = 0.f;

            #pragma unroll
            for (int nf = 0; nf < 22; nf++) {
                int cb = half * 176 + nf * 8 + lq;
                uint32_t b0[2], b1[2];
                b0[0] = *(const uint32_t*)&ks[cb * KS_STR + lr2];
                b0[1] = *(const uint32_t*)&ks[cb * KS_STR + lr2 + 8];
                b1[0] = *(const uint32_t*)&ks[cb * KS_STR + 16 + lr2];
                b1[1] = *(const uint32_t*)&ks[cb * KS_STR + 24 + lr2];
                mma_f16(acc[nf], aq[0], b0);
                mma_f16(acc[nf], aq[1], b1);
            }
            // masked bias (precomputed; padding cols carry -30000)
            #pragma unroll
            for (int nf = 0; nf < 22; nf++) {
                int c = half * 176 + nf * 8 + lr2;
                float2 p0 = *(const float2*)(rpb0 + c);
                float2 p1 = *(const float2*)(rpb1 + c);
                acc[nf][0] += p0.x; acc[nf][1] += p0.y;
                acc[nf][2] += p1.x; acc[nf][3] += p1.y;
            }
            // row max
            float h0 = -1e30f, h1 = -1e30f;
            #pragma unroll
            for (int nf = 0; nf < 22; nf++) {
                h0 = fmaxf(h0, fmaxf(acc[nf][0], acc[nf][1]));
                h1 = fmaxf(h1, fmaxf(acc[nf][2], acc[nf][3]));
            }
            h0 = fmaxf(h0, __shfl_xor_sync(~0u, h0, 1));
            h0 = fmaxf(h0, __shfl_xor_sync(~0u, h0, 2));
            h1 = fmaxf(h1, __shfl_xor_sync(~0u, h1, 1));
            h1 = fmaxf(h1, __shfl_xor_sync(~0u, h1, 2));
            float mn0 = fmaxf(m0, h0), mn1 = fmaxf(m1, h1);
            float sc0 = __expf(m0 - mn0), sc1 = __expf(m1 - mn1);
            m0 = mn0; m1 = mn1;
            l0 *= sc0; l1 *= sc1;
            #pragma unroll
            for (int nfv = 0; nfv < 4; nfv++) {
                out[nfv][0] *= sc0; out[nfv][1] *= sc0;
                out[nfv][2] *= sc1; out[nfv][3] *= sc1;
            }
            // fused exp + PV
            #pragma unroll
            for (int kf = 0; kf < 11; kf++) {
                float e0 = __expf(acc[2*kf][0]   - m0), e1 = __expf(acc[2*kf][1]   - m0);
                float e2 = __expf(acc[2*kf][2]   - m1), e3 = __expf(acc[2*kf][3]   - m1);
                float e4 = __expf(acc[2*kf+1][0] - m0), e5 = __expf(acc[2*kf+1][1] - m0);
                float e6 = __expf(acc[2*kf+1][2] - m1), e7 = __expf(acc[2*kf+1][3] - m1);
                l0 += e0 + e1 + e4 + e5;
                l1 += e2 + e3 + e6 + e7;
                __half2 hp;
                uint32_t ap[4];
                hp = __floats2half2_rn(e0, e1); ap[0] = *(uint32_t*)&hp;
                hp = __floats2half2_rn(e2, e3); ap[1] = *(uint32_t*)&hp;
                hp = __floats2half2_rn(e4, e5); ap[2] = *(uint32_t*)&hp;
                hp = __floats2half2_rn(e6, e7); ap[3] = *(uint32_t*)&hp;
                int kk = half * 176 + kf * 16 + lr2;
                #pragma unroll
                for (int nfv = 0; nfv < 4; nfv++) {
                    const __half* vb = &vts[(nfv * 8 + lq) * VT_STR + kk];
                    uint32_t bb[2] = { *(const uint32_t*)vb, *(const uint32_t*)(vb + 8) };
                    mma_f16(out[nfv], ap, bb);
                }
            }
        }
        l0 += __shfl_xor_sync(~0u, l0, 1); l0 += __shfl_xor_sync(~0u, l0, 2);
        l1 += __shfl_xor_sync(~0u, l1, 1); l1 += __shfl_xor_sync(~0u, l1, 2);
        float iv0 = 1.0f / l0, iv1 = 1.0f / l1;

        if (r0 < 343) {
            int th = r0 / 49, rem = r0 - th * 49, tw = rem / 7, td = rem - tw * 7;
            int o0 = b * LTOK + (((wh*7+th+3)%28) * 28 + ((ww*7+tw+3)%28)) * 28 + ((wd*7+td+3)%28);
            float* dp = d_attn + (size_t)o0 * CDIM + h * 32 + lr2;
            #pragma unroll
            for (int nfv = 0; nfv < 4; nfv++)
                *(float2*)(dp + nfv * 8) = make_float2(out[nfv][0] * iv0, out[nfv][1] * iv0);
        }
        if (r1 < 343) {
            int th = r1 / 49, rem = r1 - th * 49, tw = rem / 7, td = rem - tw * 7;
            int o1 = b * LTOK + (((wh*7+th+3)%28) * 28 + ((ww*7+tw+3)%28)) * 28 + ((wd*7+td+3)%28);
            float* dp = d_attn + (size_t)o1 * CDIM + h * 32 + lr2;
            #pragma unroll
            for (int nfv = 0; nfv < 4; nfv++)
                *(float2*)(dp + nfv * 8) = make_float2(out[nfv][2] * iv1, out[nfv][3] * iv1);
        }
    }
}

// ---------------- LN + residual ----------------
__global__ void __launch_bounds__(256) ln_res_kernel(const float* __restrict__ inp,
                                                     const float* __restrict__ res,
                                                     const float* __restrict__ g,
                                                     const float* __restrict__ bb,
                                                     float* __restrict__ out) {
    int row = blockIdx.x * 8 + (threadIdx.x >> 5);
    int lane = threadIdx.x & 31;
    const float* p = inp + (size_t)row * CDIM;
    float v[6]; float s = 0, s2 = 0;
    #pragma unroll
    for (int i = 0; i < 6; i++) {
        float x = p[lane + 32 * i];
        v[i] = x; s += x; s2 = fmaf(x, x, s2);
    }
    #pragma unroll
    for (int o = 16; o; o >>= 1) {
        s += __shfl_xor_sync(~0u, s, o); s2 += __shfl_xor_sync(~0u, s2, o);
    }
    float mean = s * (1.0f / 192.0f);
    float rstd = rsqrtf(s2 * (1.0f / 192.0f) - mean * mean + 1e-5f);
    const float* rr = res + (size_t)row * CDIM;
    float* oo = out + (size_t)row * CDIM;
    #pragma unroll
    for (int i = 0; i < 6; i++) {
        int c = lane + 32 * i;
        oo[c] = rr[c] + (v[i] - mean) * rstd * g[c] + bb[c];
    }
}

extern "C" void kernel_launch(void* const* d_in, const int* in_sizes, int n_in,
                              void* d_out, int out_size) {
    const float* x      = (const float*)d_in[0];
    const float* qkv_w  = (const float*)d_in[1];
    const float* q_bias = (const float*)d_in[2];
    const float* v_bias = (const float*)d_in[3];
    const float* lscale = (const float*)d_in[4];
    const float* cpb_w1 = (const float*)d_in[5];
    const float* cpb_b1 = (const float*)d_in[6];
    const float* cpb_w2 = (const float*)d_in[7];
    const float* proj_w = (const float*)d_in[8];
    const float* proj_b = (const float*)d_in[9];
    const float* n1g    = (const float*)d_in[10];
    const float* n1b    = (const float*)d_in[11];
    const float* fc1_w  = (const float*)d_in[12];
    const float* fc1_b  = (const float*)d_in[13];
    const float* fc2_w  = (const float*)d_in[14];
    const float* fc2_b  = (const float*)d_in[15];
    const float* n2g    = (const float*)d_in[16];
    const float* n2b    = (const float*)d_in[17];
    float* out = (float*)d_out;

    void *p_attn, *p_tmp, *p_x1, *p_hid;
    cudaGetSymbolAddress(&p_attn, d_attn);
    cudaGetSymbolAddress(&p_tmp, d_tmp);
    cudaGetSymbolAddress(&p_x1, d_x1);
    cudaGetSymbolAddress(&p_hid, d_hid);

    cudaFuncSetAttribute(attn_mma, cudaFuncAttributeMaxDynamicSharedMemorySize, 50816);

    cpb_kernel<<<275, 256>>>(cpb_w1, cpb_b1, cpb_w2);
    rpbm_kernel<<<(8 * 6 * 343 * RPB_STR + 255) / 256, 256>>>();

    gemm_mma<true, 2><<<dim3(9, 343), 256>>>(x, qkv_w, nullptr, nullptr, 192, 576, 6, q_bias, v_bias);
    attn_mma<<<768, 128, 50816>>>(lscale);
    gemm_mma<false, 0><<<dim3(3, 343), 256>>>((const float*)p_attn, proj_w, proj_b,
                                              (float*)p_tmp, 192, 192, 6, nullptr, nullptr);
    ln_res_kernel<<<5488, 256>>>((const float*)p_tmp, x, n1g, n1b, (float*)p_x1);
    gemm_mma<false, 1><<<dim3(12, 343), 256>>>((const float*)p_x1, fc1_w, fc1_b,
                                               (float*)p_hid, 192, 768, 6, nullptr, nullptr);
    gemm_mma<false, 0><<<dim3(3, 343), 256>>>((const float*)p_hid, fc2_w, fc2_b,
                                              (float*)p_tmp, 768, 192, 24, nullptr, nullptr);
    ln_res_kernel<<<5488, 256>>>((const float*)p_tmp, (const float*)p_x1, n2g, n2b, out);
}